// round 15
// baseline (speedup 1.0000x reference)
#include <cuda_runtime.h>

// Geometric controller: 13-float state, 33-float ref_state, 3x3 J -> 4 floats.
// Single-thread fp32 kernel, all in registers. FINAL (structural floor reached):
//  - float4 loads/store
//  - b3k[0] = third column of R (free); u1/u2 closed forms (w x e3 structure)
//  - skew2vec forms as 3 dots; b1 deriv chain removed; b1_0 unnormalized
//  - deferred normalization of db3[4] and b2[4] (rsqrt parallel with tail)
//  - 0.5 factor of e_R folded into kori
// NOTE: reference uses des_acc_ddd in ev_ddd and des_acc_dddd in ev_dddd
// (breaking the derivative-index pattern) — matched deliberately.

#define KP    16.0f
#define KV    5.6f
#define KORI_HALF (0.5f * 8.81f)
#define KW    2.54f
#define MASSC 4.34f
#define INV_M (1.0f / 4.34f)
#define GRAV  9.81f

__device__ __forceinline__ void cross3(const float* a, const float* b, float* o) {
    o[0] = a[1]*b[2] - a[2]*b[1];
    o[1] = a[2]*b[0] - a[0]*b[2];
    o[2] = a[0]*b[1] - a[1]*b[0];
}
__device__ __forceinline__ float dot3(const float* a, const float* b) {
    return a[0]*b[0] + a[1]*b[1] + a[2]*b[2];
}
__device__ __forceinline__ void normalize_s(float* v, float sign) {
    float s = sign * rsqrtf(dot3(v, v));
    v[0] *= s; v[1] *= s; v[2] *= s;
}

__global__ void __launch_bounds__(1, 1)
geometric_controller_kernel(const float4* __restrict__ state4,
                            const float* __restrict__ state_tail,
                            const float4* __restrict__ ref4,
                            const float* __restrict__ ref_tail,
                            const float4* __restrict__ J4,
                            const float* __restrict__ J_tail,
                            float4* __restrict__ out4) {
    const float m = MASSC, g = GRAV;
    const float kp = KP, kv = KV, kw = KW;

    // ---- vectorized loads: issue everything up front ----
    float4 s0 = state4[0];          // pos.xyz qx
    float4 s1 = state4[1];          // qy qz qw vel.x
    float4 s2 = state4[2];          // vel.yz w.xy
    float  s_wz = state_tail[12];   // w.z

    float4 r0 = ref4[0];
    float4 r1 = ref4[1];
    float4 r2 = ref4[2];
    float4 r3 = ref4[3];
    float4 r4 = ref4[4];
    float4 r5 = ref4[5];
    float4 r6 = ref4[6];
    float4 r7 = ref4[7];
    float  r_last = ref_tail[32];

    float4 j0 = J4[0];
    float4 j1 = J4[1];
    float  j8 = J_tail[8];

    // ---- unpack ----
    float pos[3] = { s0.x, s0.y, s0.z };
    float qx = s0.w, qy = s1.x, qz = s1.y, qw = s1.z;
    float vel[3] = { s1.w, s2.x, s2.y };
    float w[3]   = { s2.z, s2.w, s_wz };

    float des_pos[3] = { r0.x, r0.y, r0.z };
    float des_vel[3] = { r0.w, r1.x, r1.y };
    float des_acc[5][3] = {
        { r1.z, r1.w, r2.x },
        { r2.y, r2.z, r2.w },
        { r3.x, r3.y, r3.z },
        { r3.w, r4.x, r4.y },
        { r4.z, r4.w, r5.x }
    };
    float des_b1[4][3] = {
        { r5.y, r5.z, r5.w },
        { r6.x, r6.y, r6.z },
        { r6.w, r7.x, r7.y },
        { r7.z, r7.w, r_last }
    };
    float J[3][3] = {
        { j0.x, j0.y, j0.z },
        { j0.w, j1.x, j1.y },
        { j1.z, j1.w, j8   }
    };

    // ---- rotation matrix from quaternion (x,y,z,w) ----
    float R[3][3];
    R[0][0] = 1.f - 2.f*(qy*qy + qz*qz); R[0][1] = 2.f*(qx*qy - qz*qw);       R[0][2] = 2.f*(qx*qz + qy*qw);
    R[1][0] = 2.f*(qx*qy + qz*qw);       R[1][1] = 1.f - 2.f*(qx*qx + qz*qz); R[1][2] = 2.f*(qy*qz - qx*qw);
    R[2][0] = 2.f*(qx*qz - qy*qw);       R[2][1] = 2.f*(qy*qz + qx*qw);       R[2][2] = 1.f - 2.f*(qx*qx + qy*qy);

    // ---- b3 chain: b3k[k] = R @ (w x)^k e3, exploiting e3 structure ----
    float b3k[4][3];
    b3k[0][0] = R[0][2]; b3k[0][1] = R[1][2]; b3k[0][2] = R[2][2];
    #pragma unroll
    for (int i = 0; i < 3; i++)
        b3k[1][i] = R[i][0]*w[1] - R[i][1]*w[0];
    float u2[3] = { w[2]*w[0], w[2]*w[1], -(w[0]*w[0] + w[1]*w[1]) };
    float u3[3];
    cross3(w, u2, u3);
    #pragma unroll
    for (int i = 0; i < 3; i++) {
        b3k[2][i] = R[i][0]*u2[0] + R[i][1]*u2[1] + R[i][2]*u2[2];
        b3k[3][i] = R[i][0]*u3[0] + R[i][1]*u3[1] + R[i][2]*u3[2];
    }

    // ---- des_b3 derivative chain (direct recursion — fewest instructions) ----
    float db3[5][3];
    float thrust, thrust_d, thrust_dd, thrust_ddd;

    #pragma unroll
    for (int i = 0; i < 3; i++) {
        float gz = (i == 2) ? m*g : 0.f;
        db3[0][i] = -(kp*(pos[i]-des_pos[i]) + kv*(vel[i]-des_vel[i])) - gz + m*des_acc[0][i];
    }
    thrust = -dot3(db3[0], b3k[0]);

    float ev_d[3], ev_dd[3], ev_ddd[3], ev_dddd[3];
    float t_over_m = thrust * INV_M;
    #pragma unroll
    for (int i = 0; i < 3; i++) {
        float gz = (i == 2) ? g : 0.f;
        ev_d[i] = gz - t_over_m*b3k[0][i] - des_acc[0][i];
    }
    #pragma unroll
    for (int i = 0; i < 3; i++)
        db3[1][i] = -kp*(vel[i]-des_vel[i]) - kv*ev_d[i] + m*des_acc[1][i];
    thrust_d = -dot3(db3[1], b3k[0]) - dot3(db3[0], b3k[1]);

    #pragma unroll
    for (int i = 0; i < 3; i++)
        ev_dd[i] = (-thrust_d*b3k[0][i] - thrust*b3k[1][i]) * INV_M - des_acc[1][i];
    #pragma unroll
    for (int i = 0; i < 3; i++)
        db3[2][i] = -kp*ev_d[i] - kv*ev_dd[i] + m*des_acc[2][i];
    thrust_dd = -dot3(db3[2], b3k[0]) - 2.f*dot3(db3[1], b3k[1]) - dot3(db3[0], b3k[2]);

    // reference subtracts des_acc_ddd (index 3) here
    #pragma unroll
    for (int i = 0; i < 3; i++)
        ev_ddd[i] = (-thrust_dd*b3k[0][i] - 2.f*thrust_d*b3k[1][i] - thrust*b3k[2][i]) * INV_M - des_acc[3][i];
    #pragma unroll
    for (int i = 0; i < 3; i++)
        db3[3][i] = -kp*ev_dd[i] - kv*ev_ddd[i] + m*des_acc[3][i];
    thrust_ddd = -dot3(db3[3], b3k[0]) - 3.f*dot3(db3[2], b3k[1]) - 3.f*dot3(db3[1], b3k[2]) - dot3(db3[0], b3k[3]);

    // reference subtracts des_acc_dddd (index 4) here
    #pragma unroll
    for (int i = 0; i < 3; i++)
        ev_dddd[i] = (-thrust_ddd*b3k[0][i] - 3.f*thrust_dd*b3k[1][i] - 3.f*thrust_d*b3k[2][i] - thrust*b3k[3][i]) * INV_M
                     - des_acc[4][i];
    #pragma unroll
    for (int i = 0; i < 3; i++)
        db3[4][i] = -kp*ev_ddd[i] - kv*ev_dddd[i] + m*des_acc[4][i];

    // ---- normalize db3 levels 0..3; level 4 deferred ----
    #pragma unroll
    for (int k = 0; k < 4; k++) normalize_s(db3[k], -1.f);
    float s4 = rsqrtf(dot3(db3[4], db3[4]));   // dn4 = -s4 * db3raw4

    // ---- b2 chain ----
    float b2[5][3];
    cross3(db3[0], des_b1[0], b2[0]);
    {
        float t[3], t1[3];
        cross3(db3[1], des_b1[0], t);
        cross3(db3[0], des_b1[1], t1);
        #pragma unroll
        for (int i = 0; i < 3; i++) b2[1][i] = t[i] + t1[i];
    }
    {
        float a[3], b[3], c[3];
        cross3(db3[2], des_b1[0], a);
        cross3(db3[1], des_b1[1], b);
        cross3(db3[0], des_b1[2], c);
        #pragma unroll
        for (int i = 0; i < 3; i++) b2[2][i] = a[i] + 2.f*b[i] + c[i];
    }
    {
        float a[3], b[3], c[3], d[3];
        cross3(db3[3], des_b1[0], a);
        cross3(db3[2], des_b1[1], b);
        cross3(db3[1], des_b1[2], c);
        cross3(db3[0], des_b1[3], d);
        #pragma unroll
        for (int i = 0; i < 3; i++) b2[3][i] = a[i] + 3.f*b[i] + 3.f*c[i] + d[i];
    }
    {
        float a[3], b[3], c[3], d[3];
        cross3(db3[4], des_b1[0], a);   // raw — scale by -s4
        cross3(db3[3], des_b1[1], b);
        cross3(db3[2], des_b1[2], c);
        cross3(db3[1], des_b1[3], d);
        #pragma unroll
        for (int i = 0; i < 3; i++) b2[4][i] = -s4*a[i] + 4.f*b[i] + 6.f*c[i] + 4.f*d[i];
    }
    #pragma unroll
    for (int k = 0; k < 4; k++) normalize_s(b2[k], 1.f);
    float t4 = rsqrtf(dot3(b2[4], b2[4]));

    // ---- b1_0 = cross(b2n0, db3n0): unit by construction ----
    float b1_0[3];
    cross3(b2[0], db3[0], b1_0);

    // ---- angular derivatives via 3-dot skew2vec forms ----
    float w_d[3], a_d[3], j_d[3], s_d[3];

    w_d[0] = -dot3(b2[0], db3[1]);
    w_d[1] =  dot3(b1_0,  db3[1]);
    w_d[2] = -dot3(b1_0,  b2[1]);

    a_d[0] = -(dot3(b2[0], db3[2]) - w_d[1]*w_d[2]);
    a_d[1] =  (dot3(b1_0,  db3[2]) - w_d[0]*w_d[2]);
    a_d[2] = -(dot3(b1_0,  b2[2])  - w_d[0]*w_d[1]);

    j_d[0] = -(dot3(b2[0], db3[3]) - 3.f*a_d[1]*w_d[2]);
    j_d[1] =  (dot3(b1_0,  db3[3]) - 3.f*a_d[0]*w_d[2]);
    j_d[2] = -(dot3(b1_0,  b2[3])  - 3.f*a_d[0]*w_d[1]);

    s_d[0] = -((-s4)*dot3(b2[0], db3[4]) - 4.f*j_d[1]*w_d[2] - 3.f*a_d[1]*a_d[2]);
    s_d[1] =  ((-s4)*dot3(b1_0,  db3[4]) - 4.f*j_d[0]*w_d[2] - 3.f*a_d[0]*a_d[2]);
    s_d[2] = -(t4*dot3(b1_0, b2[4])      - 4.f*j_d[0]*w_d[1] - 3.f*a_d[0]*a_d[1]);

    // ---- attitude error (0.5 folded into KORI_HALF) ----
    float Rc0[3] = { R[0][0], R[1][0], R[2][0] };
    float Rc1[3] = { R[0][1], R[1][1], R[2][1] };
    float Rc2[3] = { R[0][2], R[1][2], R[2][2] };
    float e_R2[3];   // = 2 * e_R
    e_R2[0] = -(dot3(b2[0], Rc2) - dot3(Rc1, db3[0]));
    e_R2[1] =  (dot3(b1_0,  Rc2) - dot3(Rc0, db3[0]));
    e_R2[2] = -(dot3(b1_0,  Rc1) - dot3(Rc0, b2[0]));

    // ---- e_w = w - R^T (Rd0 @ w_d) ----
    float Rdw[3], t2[3], e_w[3];
    #pragma unroll
    for (int i = 0; i < 3; i++)
        Rdw[i] = b1_0[i]*w_d[0] + b2[0][i]*w_d[1] + db3[0][i]*w_d[2];
    t2[0] = dot3(Rc0, Rdw); t2[1] = dot3(Rc1, Rdw); t2[2] = dot3(Rc2, Rdw);
    #pragma unroll
    for (int i = 0; i < 3; i++) e_w[i] = w[i] - t2[i];

    // ---- moment ----
    float Jw[3];
    #pragma unroll
    for (int i = 0; i < 3; i++) Jw[i] = J[i][0]*w[0] + J[i][1]*w[1] + J[i][2]*w[2];
    float wxJw[3];
    cross3(w, Jw, wxJw);

    float M[3];
    #pragma unroll
    for (int i = 0; i < 3; i++)
        M[i] = -(KORI_HALF*e_R2[i] + kw*e_w[i]) + wxJw[i];

    float vsum[3], t1v[3], tM[3], JtM[3];
    #pragma unroll
    for (int i = 0; i < 3; i++) vsum[i] = w_d[i] - a_d[i] - j_d[i] - s_d[i];
    #pragma unroll
    for (int i = 0; i < 3; i++)
        t1v[i] = b1_0[i]*vsum[0] + b2[0][i]*vsum[1] + db3[0][i]*vsum[2];
    t2[0] = dot3(Rc0, t1v); t2[1] = dot3(Rc1, t1v); t2[2] = dot3(Rc2, t1v);
    cross3(w, t2, tM);
    #pragma unroll
    for (int i = 0; i < 3; i++)
        JtM[i] = J[i][0]*tM[0] + J[i][1]*tM[1] + J[i][2]*tM[2];
    #pragma unroll
    for (int i = 0; i < 3; i++) M[i] -= JtM[i];

    float4 o;
    o.x = fmaxf(0.f, thrust);
    o.y = M[0];
    o.z = M[1];
    o.w = M[2];
    *out4 = o;
}

extern "C" void kernel_launch(void* const* d_in, const int* in_sizes, int n_in,
                              void* d_out, int out_size) {
    const float* state = (const float*)d_in[0];
    const float* ref   = (const float*)d_in[1];
    const float* J     = (const float*)d_in[2];
    geometric_controller_kernel<<<1, 1>>>(
        (const float4*)state, state,
        (const float4*)ref,   ref,
        (const float4*)J,     J,
        (float4*)d_out);
}